// round 1
// baseline (speedup 1.0000x reference)
#include <cuda_runtime.h>

// Problem constants (from reference): B=8192, T=100, D=16, H=32, Hd=50
#define NB 8192
#define NT 100
#define ND 16
#define NH 32
#define NHD 50
#define NIN 48              // D + H
#define NEUL 10

#define TPE 8               // threads per element (roles)
#define EPB 8               // elements per block
#define NTHREADS (TPE*EPB)  // 64
#define NBLOCKS (NB/EPB)    // 1024

// Bank-conflict-free padded strides (floats). All chosen so that the 8 roles'
// row bases land on disjoint bank quads for LDS.128, and 16B-aligned.
#define W1S 52
#define W2S 52
#define W3S 36
#define Z1S 56
#define HS  40

// Accurate-enough tanh: 2 MUFU (ex2 + rcp), abs err ~1e-7.
__device__ __forceinline__ float fast_tanh(float v) {
    float ax = fabsf(v) * 2.8853900817779268f;   // 2*log2(e)
    float e;
    asm("ex2.approx.f32 %0, %1;" : "=f"(e) : "f"(ax));
    float r = 1.0f - __fdividef(2.0f, e + 1.0f); // MUFU.RCP path; e=inf -> r=1
    return copysignf(r, v);
}

__global__ __launch_bounds__(NTHREADS, 7) void latentode_kernel(
    const float* __restrict__ g_dt, const float* __restrict__ g_x,
    const float* __restrict__ g_W1, const float* __restrict__ g_b1,
    const float* __restrict__ g_W2, const float* __restrict__ g_b2,
    const float* __restrict__ g_W3, const float* __restrict__ g_b3,
    const float* __restrict__ g_W4, const float* __restrict__ g_b4,
    float* __restrict__ g_out)
{
    __shared__ float W1s[NHD * W1S];
    __shared__ float W2s[NH * W2S];
    __shared__ float W3s[2 * NH * W3S];
    __shared__ float z1buf[EPB * Z1S];
    __shared__ float hbuf[EPB * HS];

    const int tid = threadIdx.x;
    const int r   = tid & 7;      // role within element group
    const int el  = tid >> 3;     // element slot within block
    const int b   = blockIdx.x * EPB + el;

    // ---- stage weights into padded shared layouts ----
    for (int i = tid; i < NHD * NIN; i += NTHREADS)
        W1s[(i / NIN) * W1S + (i % NIN)] = g_W1[i];
    for (int i = tid; i < NH * W2S; i += NTHREADS) {
        int rr = i / W2S, cc = i - rr * W2S;
        W2s[i] = (cc < NHD) ? g_W2[rr * NHD + cc] : 0.0f;  // zero pad cols 50..51
    }
    for (int i = tid; i < 2 * NH * NH; i += NTHREADS)
        W3s[(i / NH) * W3S + (i % NH)] = g_W3[i];
    for (int i = tid; i < EPB * Z1S; i += NTHREADS)
        z1buf[i] = 0.0f;                                    // zero pads (NaN-safe)

    // ---- per-thread constants (biases + W4 slice), one-time LDG ----
    float b1r[7];
#pragma unroll
    for (int j = 0; j < 7; j++) {
        int row = r + 8 * j;
        b1r[j] = (row < NHD) ? g_b1[row] : 0.0f;
    }
    float b2r[4], b3r[8], w4r[8];
#pragma unroll
    for (int j = 0; j < 4; j++) b2r[j] = g_b2[r + 8 * j];
#pragma unroll
    for (int j = 0; j < 8; j++) { b3r[j] = g_b3[r + 8 * j]; w4r[j] = g_W4[r + 8 * j]; }
    const float b4v = g_b4[0];

    // h0 = 0
#pragma unroll
    for (int j = 0; j < 4; j++) hbuf[el * HS + r + 8 * j] = 0.0f;

    __syncthreads();

    const float* xp  = g_x  + (size_t)b * NT * ND;
    const float* dtp = g_dt + (size_t)b * NT * 2;
    float*       op  = g_out + (size_t)b * NT;

#pragma unroll 1
    for (int t = 0; t < NT; t++) {
        // x_i : 16 floats, replicated per thread (L1/L2 served)
        float xr[ND];
        const float4* xv = (const float4*)(xp + t * ND);
#pragma unroll
        for (int m = 0; m < 4; m++) {
            float4 v = xv[m];
            xr[4*m+0] = v.x; xr[4*m+1] = v.y; xr[4*m+2] = v.z; xr[4*m+3] = v.w;
        }
        float2 dv = *(const float2*)(dtp + t * 2);
        const float sc = (dv.y - dv.x) * (0.1f / 24.0f);  // STEP * DT_SCALER folded
        float y = xr[0];

#pragma unroll 1
        for (int e = 0; e < NEUL; e++) {
            // ---- load full h (replicated) ----
            float h[NH];
            const float4* hb4 = (const float4*)(hbuf + el * HS);
#pragma unroll
            for (int m = 0; m < 8; m++) {
                float4 v = hb4[m];
                h[4*m] = v.x; h[4*m+1] = v.y; h[4*m+2] = v.z; h[4*m+3] = v.w;
            }

            // ---- dy path: u = tanh(h @ W3^T + b3); dy = u @ W4^T + b4 ----
            float dyp = 0.0f;
#pragma unroll
            for (int j = 0; j < 8; j++) {
                const float4* wp = (const float4*)(W3s + (r + 8 * j) * W3S);
                float acc = b3r[j];
#pragma unroll
                for (int m = 0; m < 8; m++) {
                    float4 w = wp[m];
                    acc = fmaf(w.x, h[4*m  ], acc);
                    acc = fmaf(w.y, h[4*m+1], acc);
                    acc = fmaf(w.z, h[4*m+2], acc);
                    acc = fmaf(w.w, h[4*m+3], acc);
                }
                dyp = fmaf(w4r[j], fast_tanh(acc), dyp);
            }
            // reduce dy partials across the 8-lane group (aligned, xor-safe)
            dyp += __shfl_xor_sync(0xffffffffu, dyp, 1);
            dyp += __shfl_xor_sync(0xffffffffu, dyp, 2);
            dyp += __shfl_xor_sync(0xffffffffu, dyp, 4);
            const float dy = dyp + b4v;

            // ---- z1 = tanh([x,h] @ W1^T + b1), role-sliced rows ----
#pragma unroll
            for (int j = 0; j < 7; j++) {
                int row = r + 8 * j;
                if (row < NHD) {
                    const float4* wp = (const float4*)(W1s + row * W1S);
                    float acc = b1r[j];
#pragma unroll
                    for (int m = 0; m < 4; m++) {         // x part (cols 0..15)
                        float4 w = wp[m];
                        acc = fmaf(w.x, xr[4*m  ], acc);
                        acc = fmaf(w.y, xr[4*m+1], acc);
                        acc = fmaf(w.z, xr[4*m+2], acc);
                        acc = fmaf(w.w, xr[4*m+3], acc);
                    }
#pragma unroll
                    for (int m = 0; m < 8; m++) {         // h part (cols 16..47)
                        float4 w = wp[4 + m];
                        acc = fmaf(w.x, h[4*m  ], acc);
                        acc = fmaf(w.y, h[4*m+1], acc);
                        acc = fmaf(w.z, h[4*m+2], acc);
                        acc = fmaf(w.w, h[4*m+3], acc);
                    }
                    z1buf[el * Z1S + row] = fast_tanh(acc);
                }
            }
            __syncwarp();

            // ---- dh path: h += sc * tanh(z1 @ W2^T + b2) ----
            float acc2[4] = { b2r[0], b2r[1], b2r[2], b2r[3] };
            const float4* zp = (const float4*)(z1buf + el * Z1S);
#pragma unroll
            for (int m = 0; m < 13; m++) {               // 52 cols (pads are 0*0)
                float4 z = zp[m];
#pragma unroll
                for (int j = 0; j < 4; j++) {
                    const float4* wp = (const float4*)(W2s + (r + 8 * j) * W2S);
                    float4 w = wp[m];
                    acc2[j] = fmaf(w.x, z.x, acc2[j]);
                    acc2[j] = fmaf(w.y, z.y, acc2[j]);
                    acc2[j] = fmaf(w.z, z.z, acc2[j]);
                    acc2[j] = fmaf(w.w, z.w, acc2[j]);
                }
            }
#pragma unroll
            for (int j = 0; j < 4; j++) {
                int idx = el * HS + r + 8 * j;
                hbuf[idx] = hbuf[idx] + sc * fast_tanh(acc2[j]);  // old h still in smem
            }
            y = fmaf(sc, dy, y);
            __syncwarp();
        }
        if (r == 0) op[t] = y;
    }
}

extern "C" void kernel_launch(void* const* d_in, const int* in_sizes, int n_in,
                              void* d_out, int out_size) {
    latentode_kernel<<<NBLOCKS, NTHREADS>>>(
        (const float*)d_in[0],  // dt (8192,100,2)
        (const float*)d_in[1],  // x  (8192,100,16)
        (const float*)d_in[2],  // W1 (50,48)
        (const float*)d_in[3],  // b1 (50)
        (const float*)d_in[4],  // W2 (32,50)
        (const float*)d_in[5],  // b2 (32)
        (const float*)d_in[6],  // W3 (64,32)
        (const float*)d_in[7],  // b3 (64)
        (const float*)d_in[8],  // W4 (1,64)
        (const float*)d_in[9],  // b4 (1)
        (float*)d_out);         // out (8192,100,1) float32
}

// round 2
// speedup vs baseline: 1.6105x; 1.6105x over previous
#include <cuda_runtime.h>

typedef unsigned long long ULL;

// Problem constants: B=8192, T=100, D=16, H=32, Hd=50
#define NB 8192
#define NT 100
#define ND 16
#define NH 32
#define NHD 50
#define NEUL 10

#define TPE 8                 // threads (roles) per element group
#define GPB 8                 // groups per block
#define E 4                   // elements per group (weight-amortization batch)
#define NTHREADS (TPE*GPB)    // 64
#define EPB (GPB*E)           // 32 elements per block
#define NBLOCKS (NB/EPB)      // 256

// Weight strides (floats): == 4 (mod 8) -> 8 roles hit distinct bank quads, 16B aligned rows
#define W1R 56                // W1 rows padded 50 -> 56 (pad rows zero; removes guards)
#define W1S 52
#define W2S 52
#define W3S 36
// Activation per-element strides (floats): == 2 (mod 8) -> 4 groups spread 32B apart mod 128B
#define XS 18
#define HS 34
#define Z1S 58

__device__ __forceinline__ ULL ffma2(ULL a, ULL b, ULL c) {
    ULL d;
    asm("fma.rn.f32x2 %0, %1, %2, %3;" : "=l"(d) : "l"(a), "l"(b), "l"(c));
    return d;
}
__device__ __forceinline__ float sum2(ULL v) {
    return __uint_as_float((unsigned)v) + __uint_as_float((unsigned)(v >> 32));
}

// Accurate tanh: ex2 + rcp MUFUs, abs err ~1e-7
__device__ __forceinline__ float fast_tanh(float v) {
    float ax = fabsf(v) * 2.8853900817779268f;   // 2*log2(e)
    float e;
    asm("ex2.approx.f32 %0, %1;" : "=f"(e) : "f"(ax));
    float r = 1.0f - __fdividef(2.0f, e + 1.0f);
    return copysignf(r, v);
}

__global__ __launch_bounds__(NTHREADS, 2) void latentode_kernel(
    const float* __restrict__ g_dt, const float* __restrict__ g_x,
    const float* __restrict__ g_W1, const float* __restrict__ g_b1,
    const float* __restrict__ g_W2, const float* __restrict__ g_b2,
    const float* __restrict__ g_W3, const float* __restrict__ g_b3,
    const float* __restrict__ g_W4, const float* __restrict__ g_b4,
    float* __restrict__ g_out)
{
    __shared__ float W1s[W1R * W1S];      // 2912 fl
    __shared__ float W2s[NH * W2S];       // 1664 fl
    __shared__ float W3s[2 * NH * W3S];   // 2304 fl
    __shared__ float xs [EPB * XS];       // 576 fl
    __shared__ float hs [EPB * HS];       // 1088 fl
    __shared__ float z1s[EPB * Z1S];      // 1856 fl

    const int tid = threadIdx.x;
    const int r   = tid & 7;              // role
    const int g   = tid >> 3;             // group in block
    const int elb = g * E;                // first element slot of this group
    const int b0  = blockIdx.x * EPB + elb;
    const int bb0 = blockIdx.x * EPB;

    // ---- stage weights (zero-padded) ----
    for (int i = tid; i < W1R * W1S; i += NTHREADS) {
        int row = i / W1S, col = i - row * W1S;
        W1s[i] = (row < NHD && col < ND + NH) ? g_W1[row * (ND + NH) + col] : 0.0f;
    }
    for (int i = tid; i < NH * W2S; i += NTHREADS) {
        int row = i / W2S, col = i - row * W2S;
        W2s[i] = (col < NHD) ? g_W2[row * NHD + col] : 0.0f;
    }
    for (int i = tid; i < 2 * NH * W3S; i += NTHREADS) {
        int row = i / W3S, col = i - row * W3S;
        W3s[i] = (col < NH) ? g_W3[row * NH + col] : 0.0f;
    }
    for (int i = tid; i < EPB * Z1S; i += NTHREADS) z1s[i] = 0.0f;
    for (int i = tid; i < EPB * HS;  i += NTHREADS) hs[i]  = 0.0f;

    // ---- per-thread constants ----
    float b1r[7];
#pragma unroll
    for (int j = 0; j < 7; j++) { int row = r + 8 * j; b1r[j] = (row < NHD) ? g_b1[row] : 0.0f; }
    float b2r[4], b3r[8], w4r[8];
#pragma unroll
    for (int j = 0; j < 4; j++) b2r[j] = g_b2[r + 8 * j];
#pragma unroll
    for (int j = 0; j < 8; j++) { b3r[j] = g_b3[r + 8 * j]; w4r[j] = g_W4[r + 8 * j]; }
    const float b4v = g_b4[0];

    __syncthreads();

    const float* hb = hs  + elb * HS;
    const float* xb = xs  + elb * XS;
    const float* zb = z1s + elb * Z1S;

#pragma unroll 1
    for (int t = 0; t < NT; t++) {
        // stage x for all 32 elements of the block: 128 float4 / 64 threads
        for (int i = tid; i < EPB * ND / 4; i += NTHREADS) {
            int el = i >> 2, c = i & 3;
            float4 v = *(const float4*)(g_x + ((size_t)(bb0 + el)) * NT * ND + (size_t)t * ND + 4 * c);
            float* dst = xs + el * XS + 4 * c;
            dst[0] = v.x; dst[1] = v.y; dst[2] = v.z; dst[3] = v.w;
        }
        float sc[E], y[E];
#pragma unroll
        for (int e = 0; e < E; e++) {
            float2 dv = *(const float2*)(g_dt + ((size_t)(b0 + e)) * NT * 2 + (size_t)t * 2);
            sc[e] = (dv.y - dv.x) * (0.1f / 24.0f);   // STEP * DT_SCALER folded
        }
        __syncthreads();
#pragma unroll
        for (int e = 0; e < E; e++) y[e] = xb[e * XS];  // y0 = x[:,0]

#pragma unroll 1
        for (int it = 0; it < NEUL; it++) {
            // ================= W3 path: u = tanh(h @ W3^T + b3), dy = u @ W4^T =================
            ULL a3[8][E];
#pragma unroll
            for (int j = 0; j < 8; j++)
#pragma unroll
                for (int e = 0; e < E; e++) a3[j][e] = 0ULL;

            const float* w3 = W3s + r * W3S;
#pragma unroll 2
            for (int kp = 0; kp < 8; kp++) {          // 8 steps x 4 cols
                ULL h0[E], h1[E];
#pragma unroll
                for (int e = 0; e < E; e++) {
                    const ULL* p = (const ULL*)(hb + e * HS + 4 * kp);
                    h0[e] = p[0]; h1[e] = p[1];
                }
#pragma unroll
                for (int j = 0; j < 8; j++) {
                    ulonglong2 w = *(const ulonglong2*)(w3 + j * 8 * W3S + 4 * kp);
#pragma unroll
                    for (int e = 0; e < E; e++) {
                        a3[j][e] = ffma2(w.x, h0[e], a3[j][e]);
                        a3[j][e] = ffma2(w.y, h1[e], a3[j][e]);
                    }
                }
            }
            float dyp[E] = {0.0f, 0.0f, 0.0f, 0.0f};
#pragma unroll
            for (int j = 0; j < 8; j++)
#pragma unroll
                for (int e = 0; e < E; e++)
                    dyp[e] = fmaf(w4r[j], fast_tanh(sum2(a3[j][e]) + b3r[j]), dyp[e]);
#pragma unroll
            for (int e = 0; e < E; e++) {
                dyp[e] += __shfl_xor_sync(0xffffffffu, dyp[e], 1);
                dyp[e] += __shfl_xor_sync(0xffffffffu, dyp[e], 2);
                dyp[e] += __shfl_xor_sync(0xffffffffu, dyp[e], 4);
            }

            // ================= W1 path: z1 = tanh([x,h] @ W1^T + b1) =================
            ULL a1[7][E];
#pragma unroll
            for (int j = 0; j < 7; j++)
#pragma unroll
                for (int e = 0; e < E; e++) a1[j][e] = 0ULL;

            const float* w1 = W1s + r * W1S;
#pragma unroll 2
            for (int kp = 0; kp < 4; kp++) {          // x part: cols 0..15
                ULL x0[E], x1[E];
#pragma unroll
                for (int e = 0; e < E; e++) {
                    const ULL* p = (const ULL*)(xb + e * XS + 4 * kp);
                    x0[e] = p[0]; x1[e] = p[1];
                }
#pragma unroll
                for (int j = 0; j < 7; j++) {
                    ulonglong2 w = *(const ulonglong2*)(w1 + j * 8 * W1S + 4 * kp);
#pragma unroll
                    for (int e = 0; e < E; e++) {
                        a1[j][e] = ffma2(w.x, x0[e], a1[j][e]);
                        a1[j][e] = ffma2(w.y, x1[e], a1[j][e]);
                    }
                }
            }
#pragma unroll 2
            for (int kp = 0; kp < 8; kp++) {          // h part: cols 16..47
                ULL h0[E], h1[E];
#pragma unroll
                for (int e = 0; e < E; e++) {
                    const ULL* p = (const ULL*)(hb + e * HS + 4 * kp);
                    h0[e] = p[0]; h1[e] = p[1];
                }
#pragma unroll
                for (int j = 0; j < 7; j++) {
                    ulonglong2 w = *(const ulonglong2*)(w1 + j * 8 * W1S + ND + 4 * kp);
#pragma unroll
                    for (int e = 0; e < E; e++) {
                        a1[j][e] = ffma2(w.x, h0[e], a1[j][e]);
                        a1[j][e] = ffma2(w.y, h1[e], a1[j][e]);
                    }
                }
            }
#pragma unroll
            for (int j = 0; j < 7; j++) {
                int row = r + 8 * j;                  // rows 50..55 write tanh(0)=0 into pad
#pragma unroll
                for (int e = 0; e < E; e++)
                    z1s[(elb + e) * Z1S + row] = fast_tanh(sum2(a1[j][e]) + b1r[j]);
            }
            __syncwarp();

            // ================= W2 path: h += sc * tanh(z1 @ W2^T + b2) =================
            ULL a2[4][E];
#pragma unroll
            for (int j = 0; j < 4; j++)
#pragma unroll
                for (int e = 0; e < E; e++) a2[j][e] = 0ULL;

            const float* w2 = W2s + r * W2S;
#pragma unroll 2
            for (int kp = 0; kp < 13; kp++) {         // 13 steps x 4 cols = 52 (pads are 0)
                ULL z0[E], z1v[E];
#pragma unroll
                for (int e = 0; e < E; e++) {
                    const ULL* p = (const ULL*)(zb + e * Z1S + 4 * kp);
                    z0[e] = p[0]; z1v[e] = p[1];
                }
#pragma unroll
                for (int j = 0; j < 4; j++) {
                    ulonglong2 w = *(const ulonglong2*)(w2 + j * 8 * W2S + 4 * kp);
#pragma unroll
                    for (int e = 0; e < E; e++) {
                        a2[j][e] = ffma2(w.x, z0[e], a2[j][e]);
                        a2[j][e] = ffma2(w.y, z1v[e], a2[j][e]);
                    }
                }
            }
#pragma unroll
            for (int j = 0; j < 4; j++) {
                int row = r + 8 * j;
#pragma unroll
                for (int e = 0; e < E; e++) {
                    float* hp = (float*)&hs[(elb + e) * HS + row];
                    *hp = *hp + sc[e] * fast_tanh(sum2(a2[j][e]) + b2r[j]);
                }
            }
#pragma unroll
            for (int e = 0; e < E; e++) y[e] = fmaf(sc[e], dyp[e] + b4v, y[e]);
            __syncwarp();
        }

        if (r == 0) {
#pragma unroll
            for (int e = 0; e < E; e++) g_out[((size_t)(b0 + e)) * NT + t] = y[e];
        }
    }
}

extern "C" void kernel_launch(void* const* d_in, const int* in_sizes, int n_in,
                              void* d_out, int out_size) {
    latentode_kernel<<<NBLOCKS, NTHREADS>>>(
        (const float*)d_in[0],  // dt (8192,100,2)
        (const float*)d_in[1],  // x  (8192,100,16)
        (const float*)d_in[2],  // W1 (50,48)
        (const float*)d_in[3],  // b1 (50)
        (const float*)d_in[4],  // W2 (32,50)
        (const float*)d_in[5],  // b2 (32)
        (const float*)d_in[6],  // W3 (64,32)
        (const float*)d_in[7],  // b3 (64)
        (const float*)d_in[8],  // W4 (1,64)
        (const float*)d_in[9],  // b4 (1)
        (float*)d_out);         // out (8192,100) float32
}